// round 1
// baseline (speedup 1.0000x reference)
#include <cuda_runtime.h>
#include <cuda_bf16.h>
#include <math.h>

#define N 192
#define C 256
#define K 16
#define P_COUNT 2304      // K * (N/K)^2
#define NEG_COUNT 34560   // N*N - P_COUNT
#define MARGIN 0.05f
#define EPS 1e-6f

// Scratch (device globals: no allocation allowed)
__device__ float g_p[P_COUNT];
__device__ float g_n[NEG_COUNT];

// ---------------------------------------------------------------------------
// Kernel 1: compute pairwise cosine distance and scatter into ordered p / n
// arrays matching jnp.nonzero(flatten(mask)) row-major ordering.
// Grid: N blocks (one per row i), 192 threads (6 warps). Warp w handles
// columns j = w, w+6, ... Lanes cooperate on the length-256 dot product.
// ---------------------------------------------------------------------------
__global__ __launch_bounds__(192, 8)
void dist_scatter_kernel(const float* __restrict__ pred,
                         const int* __restrict__ target) {
    const int i   = blockIdx.x;
    const int tid = threadIdx.x;
    const int warp = tid >> 5;
    const int lane = tid & 31;

    __shared__ float rowi[C];
    __shared__ int   tgt[N];
    __shared__ float ssi_sh;
    __shared__ int   posOff_sh;

    for (int c = tid; c < C; c += 192) rowi[c] = pred[i * C + c];
    for (int t = tid; t < N; t += 192) tgt[t] = target[t];
    __syncthreads();

    if (tid == 0) {
        // total count per label -> prefix of positive counts over rows < i
        int cnt[K];
        #pragma unroll
        for (int k = 0; k < K; k++) cnt[k] = 0;
        for (int r = 0; r < N; r++) cnt[tgt[r] & (K - 1)]++;
        int po = 0;
        for (int r = 0; r < i; r++) po += cnt[tgt[r] & (K - 1)];
        posOff_sh = po;
        float ss = 0.f;
        for (int c = 0; c < C; c++) ss += rowi[c] * rowi[c];
        ssi_sh = ss;
    }
    __syncthreads();

    const int   Li     = tgt[i];
    const float ssi    = ssi_sh;
    const int   posOff = posOff_sh;
    const int   negOff = i * N - posOff;

    const float4* ri4 = (const float4*)rowi;

    for (int j = warp; j < N; j += 6) {
        const float4* pj = (const float4*)(pred + j * C);
        float4 v0 = pj[lane * 2];
        float4 v1 = pj[lane * 2 + 1];
        float4 r0 = ri4[lane * 2];
        float4 r1 = ri4[lane * 2 + 1];

        float dot = v0.x * r0.x + v0.y * r0.y + v0.z * r0.z + v0.w * r0.w
                  + v1.x * r1.x + v1.y * r1.y + v1.z * r1.z + v1.w * r1.w;
        float ssj = v0.x * v0.x + v0.y * v0.y + v0.z * v0.z + v0.w * v0.w
                  + v1.x * v1.x + v1.y * v1.y + v1.z * v1.z + v1.w * v1.w;

        // prefix rank: #{j' < j : tgt[j'] == Li}
        int pre = 0;
        for (int jj = lane; jj < j; jj += 32) pre += (tgt[jj] == Li) ? 1 : 0;

        #pragma unroll
        for (int off = 16; off > 0; off >>= 1) {
            dot += __shfl_xor_sync(0xFFFFFFFFu, dot, off);
            ssj += __shfl_xor_sync(0xFFFFFFFFu, ssj, off);
            pre += __shfl_xor_sync(0xFFFFFFFFu, pre, off);
        }

        if (lane == 0) {
            float denom = fmaxf(sqrtf(ssi * ssj), EPS);
            float dist  = 0.5f - 0.5f * dot / denom;
            if (tgt[j] == Li) {
                g_p[posOff + pre] = dist;
            } else {
                g_n[negOff + (j - pre)] = dist;
            }
        }
    }
}

// ---------------------------------------------------------------------------
// Kernel 2: out[m][k] = max(0, MARGIN + p[k] - n[m])   (NEG_COUNT x P_COUNT)
// Pure streaming-write kernel: 318.5 MB of fp32. Each thread caches 3 float4
// of p in registers, iterates ROWS_PER_BLK output rows, float4 streaming
// stores (__stcs) to avoid L2 pollution.
// ---------------------------------------------------------------------------
#define ROWS_PER_BLK 16
#define T2 192   // 576 float4 per row = 192 threads * 3

__global__ __launch_bounds__(T2, 8)
void outer_kernel(float* __restrict__ out) {
    const int tid = threadIdx.x;
    const int m0  = blockIdx.x * ROWS_PER_BLK;

    const float4* p4 = (const float4*)g_p;
    float4 pv0 = p4[tid];
    float4 pv1 = p4[tid + 192];
    float4 pv2 = p4[tid + 384];

    #pragma unroll
    for (int r = 0; r < ROWS_PER_BLK; r++) {
        const int m = m0 + r;
        const float c = MARGIN - g_n[m];
        float4* o = (float4*)(out + (size_t)m * P_COUNT);

        float4 w0, w1, w2;
        w0.x = fmaxf(0.f, pv0.x + c); w0.y = fmaxf(0.f, pv0.y + c);
        w0.z = fmaxf(0.f, pv0.z + c); w0.w = fmaxf(0.f, pv0.w + c);
        w1.x = fmaxf(0.f, pv1.x + c); w1.y = fmaxf(0.f, pv1.y + c);
        w1.z = fmaxf(0.f, pv1.z + c); w1.w = fmaxf(0.f, pv1.w + c);
        w2.x = fmaxf(0.f, pv2.x + c); w2.y = fmaxf(0.f, pv2.y + c);
        w2.z = fmaxf(0.f, pv2.z + c); w2.w = fmaxf(0.f, pv2.w + c);

        __stcs(&o[tid],       w0);
        __stcs(&o[tid + 192], w1);
        __stcs(&o[tid + 384], w2);
    }
}

extern "C" void kernel_launch(void* const* d_in, const int* in_sizes, int n_in,
                              void* d_out, int out_size) {
    const float* pred   = (const float*)d_in[0];
    const int*   target = (const int*)d_in[1];
    float*       out    = (float*)d_out;

    dist_scatter_kernel<<<N, 192>>>(pred, target);
    outer_kernel<<<NEG_COUNT / ROWS_PER_BLK, T2>>>(out);
}